// round 1
// baseline (speedup 1.0000x reference)
#include <cuda_runtime.h>

#define NMAX 50176
#define LN_EPS 1e-5f

// Scratch for q,k,v projections (zero-init .bss, no runtime allocation)
__device__ float g_q[NMAX * 64];
__device__ float g_k[NMAX * 64];
__device__ float g_v[NMAX * 64];

__device__ __forceinline__ void reduce16(float& a, float& b) {
#pragma unroll
    for (int off = 8; off > 0; off >>= 1) {
        a += __shfl_xor_sync(0xffffffffu, a, off, 16);
        b += __shfl_xor_sync(0xffffffffu, b, off, 16);
    }
}

// ---------------------------------------------------------------------------
// Kernel A: q/k/v = features @ W + b   (N x 64) @ (64 x 64), 3 weight sets
// Block: 1024 threads, 16 rows per block. Thread (r = t/64, c = t%64)
// computes q,k,v for one (row, col).
// ---------------------------------------------------------------------------
__global__ __launch_bounds__(1024) void qkv_kernel(
    const float* __restrict__ feat, int N,
    const float* __restrict__ wq, const float* __restrict__ bq,
    const float* __restrict__ wk, const float* __restrict__ bk,
    const float* __restrict__ wv, const float* __restrict__ bv)
{
    extern __shared__ float sm[];
    float* swq = sm;              // 4096
    float* swk = swq + 4096;      // 4096
    float* swv = swk + 4096;      // 4096
    float* sb  = swv + 4096;      // 192
    float* sf  = sb + 192;        // 1024 (16 rows x 64)
    const int t = threadIdx.x;

    for (int j = t; j < 4096; j += 1024) {
        swq[j] = wq[j]; swk[j] = wk[j]; swv[j] = wv[j];
    }
    if (t < 64) { sb[t] = bq[t]; sb[64 + t] = bk[t]; sb[128 + t] = bv[t]; }

    const int row0 = blockIdx.x * 16;
    const int gi = row0 * 64 + t;
    sf[t] = (gi < N * 64) ? feat[gi] : 0.f;
    __syncthreads();

    const int r = t >> 6, c = t & 63;
    float aq = sb[c], ak = sb[64 + c], av = sb[128 + c];
    const float* fr = sf + r * 64;
#pragma unroll 16
    for (int i = 0; i < 64; i++) {
        float f = fr[i];
        aq = fmaf(f, swq[i * 64 + c], aq);
        ak = fmaf(f, swk[i * 64 + c], ak);
        av = fmaf(f, swv[i * 64 + c], av);
    }
    const int row = row0 + r;
    if (row < N) {
        g_q[row * 64 + c] = aq;
        g_k[row * 64 + c] = ak;
        g_v[row * 64 + c] = av;
    }
}

// ---------------------------------------------------------------------------
// Kernel B: fully fused per-point transformer.
// Block: 256 threads = 4 point-groups of 64 threads; 4 serial iterations
// => 16 points per block. Within a point group of 64 threads:
//   u = t % 64, rq = u/16 (owns rows rq*4..rq*4+3), cg = u%16 (cols cg*4..+3)
// Per-point (16 x 64) tiles live in SMEM; GEMMs use 4x4 register blocking.
// ---------------------------------------------------------------------------
__global__ __launch_bounds__(256) void pt_kernel(
    const float* __restrict__ points, const float* __restrict__ feat,
    const int* __restrict__ nbr, int N,
    const float* __restrict__ wp,  const float* __restrict__ wg1,
    const float* __restrict__ wg2, const float* __restrict__ wo,
    const float* __restrict__ bp,  const float* __restrict__ gp,
    const float* __restrict__ betap,
    const float* __restrict__ bg1, const float* __restrict__ gg,
    const float* __restrict__ betag,
    const float* __restrict__ bg2, const float* __restrict__ bo,
    float* __restrict__ out)
{
    extern __shared__ float sm[];
    float* swg1  = sm;               // 4096
    float* swg2  = swg1 + 4096;      // 4096
    float* swo   = swg2 + 4096;      // 4096
    float* swp   = swo  + 4096;      // 192 (3 x 64)
    float* sbias = swp  + 192;       // 512: bp|gp|betap|bg1|gg|betag|bg2|bo
    float* spb   = sbias + 512;      // 4 x 1024  p tiles
    float* sgvb  = spb  + 4096;      // 4 x 1024  gathered v tiles
    float* sbfb  = sgvb + 4096;      // 4 x 1024  attn/h/w scratch tiles
    float* soutb = sbfb + 4096;      // 4 x 64    per-point out vectors

    const int t = threadIdx.x;
    for (int j = t; j < 4096; j += 256) {
        swg1[j] = wg1[j]; swg2[j] = wg2[j]; swo[j] = wo[j];
    }
    for (int j = t; j < 192; j += 256) swp[j] = wp[j];
    if (t < 64) {
        sbias[t]       = bp[t];
        sbias[64 + t]  = gp[t];
        sbias[128 + t] = betap[t];
        sbias[192 + t] = bg1[t];
        sbias[256 + t] = gg[t];
        sbias[320 + t] = betag[t];
        sbias[384 + t] = bg2[t];
        sbias[448 + t] = bo[t];
    }
    __syncthreads();

    const int pg = t >> 6;
    const int u  = t & 63;
    const int rq = u >> 4;
    const int cg = u & 15;
    const int c0 = cg << 2;

    float* mp   = spb  + pg * 1024;
    float* mgv  = sgvb + pg * 1024;
    float* mbf  = sbfb + pg * 1024;
    float* mout = soutb + pg * 64;

    for (int iter = 0; iter < 4; iter++) {
        const int n = blockIdx.x * 16 + iter * 4 + pg;
        const bool valid = (n < N);
        const int nn = valid ? n : 0;

        const float4 q4 = *(const float4*)(g_q + nn * 64 + c0);
        const float ptx = points[nn * 3 + 0];
        const float pty = points[nn * 3 + 1];
        const float ptz = points[nn * 3 + 2];

        // --- gather + positional encoding (LN+relu) + attn_in, 4 rows ---
#pragma unroll
        for (int jj = 0; jj < 4; jj++) {
            const int r = rq * 4 + jj;
            const int id = nbr[nn * 16 + r];
            const float rx = points[id * 3 + 0] - ptx;
            const float ry = points[id * 3 + 1] - pty;
            const float rz = points[id * 3 + 2] - ptz;
            float pr[4];
#pragma unroll
            for (int j = 0; j < 4; j++) {
                const int c = c0 + j;
                pr[j] = fmaf(rx, swp[c],
                        fmaf(ry, swp[64 + c],
                        fmaf(rz, swp[128 + c], sbias[c])));
            }
            float s1 = pr[0] + pr[1] + pr[2] + pr[3];
            float s2 = pr[0]*pr[0] + pr[1]*pr[1] + pr[2]*pr[2] + pr[3]*pr[3];
            reduce16(s1, s2);
            const float mean = s1 * 0.015625f;
            const float var  = s2 * 0.015625f - mean * mean;
            const float inv  = rsqrtf(var + LN_EPS);

            const float4 gk4 = *(const float4*)(g_k + id * 64 + c0);
            const float4 gv4 = *(const float4*)(g_v + id * 64 + c0);

            float pv[4];
#pragma unroll
            for (int j = 0; j < 4; j++) {
                const int c = c0 + j;
                pv[j] = fmaxf(fmaf((pr[j] - mean) * inv, sbias[64 + c],
                                   sbias[128 + c]), 0.f);
            }
            *(float4*)(mp + r * 64 + c0) =
                make_float4(pv[0], pv[1], pv[2], pv[3]);
            *(float4*)(mbf + r * 64 + c0) =
                make_float4(q4.x - gk4.x + pv[0], q4.y - gk4.y + pv[1],
                            q4.z - gk4.z + pv[2], q4.w - gk4.w + pv[3]);
            *(float4*)(mgv + r * 64 + c0) = gv4;
        }
        __syncthreads();

        // --- GEMM1: h = relu(LN(attn_in @ wg1 + bg1)) ---
        float acc[4][4];
#pragma unroll
        for (int jj = 0; jj < 4; jj++)
#pragma unroll
            for (int j = 0; j < 4; j++) acc[jj][j] = sbias[192 + c0 + j];

        const float* mrow = mbf + (rq * 4) * 64;
#pragma unroll 8
        for (int i = 0; i < 64; i++) {
            const float4 w4 = *(const float4*)(swg1 + i * 64 + c0);
#pragma unroll
            for (int jj = 0; jj < 4; jj++) {
                const float a = mrow[jj * 64 + i];
                acc[jj][0] = fmaf(a, w4.x, acc[jj][0]);
                acc[jj][1] = fmaf(a, w4.y, acc[jj][1]);
                acc[jj][2] = fmaf(a, w4.z, acc[jj][2]);
                acc[jj][3] = fmaf(a, w4.w, acc[jj][3]);
            }
        }
        float hv[4][4];
#pragma unroll
        for (int jj = 0; jj < 4; jj++) {
            float s1 = acc[jj][0] + acc[jj][1] + acc[jj][2] + acc[jj][3];
            float s2 = acc[jj][0]*acc[jj][0] + acc[jj][1]*acc[jj][1]
                     + acc[jj][2]*acc[jj][2] + acc[jj][3]*acc[jj][3];
            reduce16(s1, s2);
            const float mean = s1 * 0.015625f;
            const float var  = s2 * 0.015625f - mean * mean;
            const float inv  = rsqrtf(var + LN_EPS);
#pragma unroll
            for (int j = 0; j < 4; j++) {
                const int c = c0 + j;
                hv[jj][j] = fmaxf(fmaf((acc[jj][j] - mean) * inv,
                                       sbias[256 + c], sbias[320 + c]), 0.f);
            }
        }
        __syncthreads();
#pragma unroll
        for (int jj = 0; jj < 4; jj++)
            *(float4*)(mbf + (rq * 4 + jj) * 64 + c0) =
                make_float4(hv[jj][0], hv[jj][1], hv[jj][2], hv[jj][3]);
        __syncthreads();

        // --- GEMM2: w = h @ wg2 + bg2 ---
        float acc2[4][4];
#pragma unroll
        for (int jj = 0; jj < 4; jj++)
#pragma unroll
            for (int j = 0; j < 4; j++) acc2[jj][j] = sbias[384 + c0 + j];
#pragma unroll 8
        for (int i = 0; i < 64; i++) {
            const float4 w4 = *(const float4*)(swg2 + i * 64 + c0);
#pragma unroll
            for (int jj = 0; jj < 4; jj++) {
                const float a = mrow[jj * 64 + i];
                acc2[jj][0] = fmaf(a, w4.x, acc2[jj][0]);
                acc2[jj][1] = fmaf(a, w4.y, acc2[jj][1]);
                acc2[jj][2] = fmaf(a, w4.z, acc2[jj][2]);
                acc2[jj][3] = fmaf(a, w4.w, acc2[jj][3]);
            }
        }
        __syncthreads();
#pragma unroll
        for (int jj = 0; jj < 4; jj++)
            *(float4*)(mbf + (rq * 4 + jj) * 64 + c0) =
                make_float4(acc2[jj][0], acc2[jj][1], acc2[jj][2], acc2[jj][3]);
        __syncthreads();

        // --- softmax over K (axis=1) + weighted sum; thread u owns column u ---
        float mx = -3.4e38f;
#pragma unroll
        for (int kk = 0; kk < 16; kk++) mx = fmaxf(mx, mbf[kk * 64 + u]);
        float s = 0.f, o = 0.f;
#pragma unroll
        for (int kk = 0; kk < 16; kk++) {
            const float e = __expf(mbf[kk * 64 + u] - mx);
            s += e;
            o = fmaf(e, mgv[kk * 64 + u] + mp[kk * 64 + u], o);
        }
        mout[u] = o / s;
        __syncthreads();

        // --- final: out @ wo + bo + residual ---
        float acc3 = sbias[448 + u];
#pragma unroll 16
        for (int i = 0; i < 64; i++)
            acc3 = fmaf(mout[i], swo[i * 64 + u], acc3);
        if (valid) out[n * 64 + u] = acc3 + feat[n * 64 + u];
        __syncthreads();   // protect smem tiles before next iteration
    }
}

// ---------------------------------------------------------------------------
extern "C" void kernel_launch(void* const* d_in, const int* in_sizes, int n_in,
                              void* d_out, int out_size)
{
    const float* points = (const float*)d_in[0];
    const float* feat   = (const float*)d_in[1];
    const int*   nbr    = (const int*)  d_in[2];
    const float* wq     = (const float*)d_in[3];
    const float* bq     = (const float*)d_in[4];
    const float* wk     = (const float*)d_in[5];
    const float* bk     = (const float*)d_in[6];
    const float* wv     = (const float*)d_in[7];
    const float* bv     = (const float*)d_in[8];
    const float* wp     = (const float*)d_in[9];
    const float* bp     = (const float*)d_in[10];
    const float* gp     = (const float*)d_in[11];
    const float* betap  = (const float*)d_in[12];
    const float* wg1    = (const float*)d_in[13];
    const float* bg1    = (const float*)d_in[14];
    const float* gg     = (const float*)d_in[15];
    const float* betag  = (const float*)d_in[16];
    const float* wg2    = (const float*)d_in[17];
    const float* bg2    = (const float*)d_in[18];
    const float* wo     = (const float*)d_in[19];
    const float* bo     = (const float*)d_in[20];
    float* out = (float*)d_out;

    const int N = in_sizes[0] / 3;

    const int smemA = (3 * 4096 + 192 + 1024) * 4;                    // 54016
    const int smemB = (3 * 4096 + 192 + 512 + 3 * 4096 + 256) * 4;    // 102144
    cudaFuncSetAttribute(qkv_kernel,
                         cudaFuncAttributeMaxDynamicSharedMemorySize, smemA);
    cudaFuncSetAttribute(pt_kernel,
                         cudaFuncAttributeMaxDynamicSharedMemorySize, smemB);

    const int nb = (N + 15) / 16;
    qkv_kernel<<<nb, 1024, smemA>>>(feat, N, wq, bq, wk, bk, wv, bv);
    pt_kernel<<<nb, 256, smemB>>>(points, feat, nbr, N,
                                  wp, wg1, wg2, wo,
                                  bp, gp, betap, bg1, gg, betag, bg2, bo,
                                  out);
}

// round 2
// speedup vs baseline: 1.1664x; 1.1664x over previous
#include <cuda_runtime.h>

#define NMAX 50176
#define LN_EPS 1e-5f

__device__ float g_q[NMAX * 64];
__device__ float g_k[NMAX * 64];
__device__ float g_v[NMAX * 64];

__device__ __forceinline__ void reduce16(float& a, float& b) {
#pragma unroll
    for (int off = 8; off > 0; off >>= 1) {
        a += __shfl_xor_sync(0xffffffffu, a, off, 16);
        b += __shfl_xor_sync(0xffffffffu, b, off, 16);
    }
}

// ---------------------------------------------------------------------------
// Kernel A: q/k/v = features @ W + b. 1024 threads, 64 rows/block.
// Thread (r = t>>4, cg = t&15) computes 4 columns for q,k,v (12 outputs).
// Inner loop: 13 LDS.128 per 48 FFMA.
// ---------------------------------------------------------------------------
__global__ __launch_bounds__(1024, 1) void qkv_kernel(
    const float* __restrict__ feat, int N,
    const float* __restrict__ wq, const float* __restrict__ bq,
    const float* __restrict__ wk, const float* __restrict__ bk,
    const float* __restrict__ wv, const float* __restrict__ bv)
{
    extern __shared__ float sm[];
    float* swq = sm;              // 4096
    float* swk = swq + 4096;      // 4096
    float* swv = swk + 4096;      // 4096
    float* sb  = swv + 4096;      // 192
    float* sf  = sb + 192;        // 4096 (64 rows x 64)
    const int t = threadIdx.x;

    for (int j = t; j < 4096; j += 1024) {
        swq[j] = wq[j]; swk[j] = wk[j]; swv[j] = wv[j];
    }
    if (t < 64) { sb[t] = bq[t]; sb[64 + t] = bk[t]; sb[128 + t] = bv[t]; }

    const int row0 = blockIdx.x * 64;
    {
        const int gi = row0 * 64 + t * 4;   // one float4 per thread
        float4 f4 = make_float4(0.f, 0.f, 0.f, 0.f);
        if (gi + 3 < N * 64) f4 = *(const float4*)(feat + gi);
        *(float4*)(sf + t * 4) = f4;
    }
    __syncthreads();

    const int r  = t >> 4;
    const int c0 = (t & 15) << 2;

    float aq[4], ak[4], av[4];
#pragma unroll
    for (int j = 0; j < 4; j++) {
        aq[j] = sb[c0 + j]; ak[j] = sb[64 + c0 + j]; av[j] = sb[128 + c0 + j];
    }

    const float* fr = sf + r * 64;
#pragma unroll 2
    for (int i4 = 0; i4 < 16; i4++) {
        float a[4];
        *(float4*)a = *(const float4*)(fr + i4 * 4);
#pragma unroll
        for (int j = 0; j < 4; j++) {
            const int i = i4 * 4 + j;
            const float4 q4 = *(const float4*)(swq + i * 64 + c0);
            aq[0] = fmaf(a[j], q4.x, aq[0]); aq[1] = fmaf(a[j], q4.y, aq[1]);
            aq[2] = fmaf(a[j], q4.z, aq[2]); aq[3] = fmaf(a[j], q4.w, aq[3]);
            const float4 k4 = *(const float4*)(swk + i * 64 + c0);
            ak[0] = fmaf(a[j], k4.x, ak[0]); ak[1] = fmaf(a[j], k4.y, ak[1]);
            ak[2] = fmaf(a[j], k4.z, ak[2]); ak[3] = fmaf(a[j], k4.w, ak[3]);
            const float4 v4 = *(const float4*)(swv + i * 64 + c0);
            av[0] = fmaf(a[j], v4.x, av[0]); av[1] = fmaf(a[j], v4.y, av[1]);
            av[2] = fmaf(a[j], v4.z, av[2]); av[3] = fmaf(a[j], v4.w, av[3]);
        }
    }
    const int row = row0 + r;
    if (row < N) {
        *(float4*)(g_q + row * 64 + c0) = make_float4(aq[0], aq[1], aq[2], aq[3]);
        *(float4*)(g_k + row * 64 + c0) = make_float4(ak[0], ak[1], ak[2], ak[3]);
        *(float4*)(g_v + row * 64 + c0) = make_float4(av[0], av[1], av[2], av[3]);
    }
}

// ---------------------------------------------------------------------------
// Kernel B: fused per-point transformer. 256 threads = 4 groups x 64,
// 4 iters => 16 points/block. GEMMs: 8 LDS.128 per 64 FFMA.
// Final out@wo batched over 16 points at the end (wo from GMEM via L1).
// ---------------------------------------------------------------------------
__global__ __launch_bounds__(256, 3) void pt_kernel(
    const float* __restrict__ points, const float* __restrict__ feat,
    const int* __restrict__ nbr, int N,
    const float* __restrict__ wp,  const float* __restrict__ wg1,
    const float* __restrict__ wg2, const float* __restrict__ wo,
    const float* __restrict__ bp,  const float* __restrict__ gp,
    const float* __restrict__ betap,
    const float* __restrict__ bg1, const float* __restrict__ gg,
    const float* __restrict__ betag,
    const float* __restrict__ bg2, const float* __restrict__ bo,
    float* __restrict__ out)
{
    extern __shared__ float sm[];
    float* swg1  = sm;               // 4096
    float* swg2  = swg1 + 4096;      // 4096
    float* swp   = swg2 + 4096;      // 192
    float* sbias = swp  + 192;       // 512: bp|gp|betap|bg1|gg|betag|bg2|bo
    float* sM    = sbias + 512;      // 32: Gram matrix (16) + row-sums (4)
    float* sgvp  = sM    + 32;       // 4 x 1024  (gv + p) tiles
    float* sbf   = sgvp  + 4096;     // 4 x 1024  attn/h/w scratch
    float* smout = sbf   + 4096;     // 16 x 64   per-point out vectors

    const int t = threadIdx.x;
    for (int j = t; j < 4096; j += 256) { swg1[j] = wg1[j]; swg2[j] = wg2[j]; }
    for (int j = t; j < 192; j += 256) swp[j] = wp[j];
    if (t < 64) {
        sbias[t]       = bp[t];
        sbias[64 + t]  = gp[t];
        sbias[128 + t] = betap[t];
        sbias[192 + t] = bg1[t];
        sbias[256 + t] = gg[t];
        sbias[320 + t] = betag[t];
        sbias[384 + t] = bg2[t];
        sbias[448 + t] = bo[t];
    }
    __syncthreads();

    // Gram matrix of augmented wp rows [wp0,wp1,wp2,bp] for analytic LN stats
    if (t < 20) {
        if (t < 16) {
            const int a = t >> 2, b = t & 3;
            const float* ra = (a < 3) ? (swp + a * 64) : sbias;
            const float* rb = (b < 3) ? (swp + b * 64) : sbias;
            float s = 0.f;
            for (int c = 0; c < 64; c++) s += ra[c] * rb[c];
            sM[t] = s;
        } else {
            const int a = t - 16;
            const float* ra = (a < 3) ? (swp + a * 64) : sbias;
            float s = 0.f;
            for (int c = 0; c < 64; c++) s += ra[c];
            sM[t] = s;
        }
    }
    __syncthreads();

    const int pg = t >> 6;          // point group 0..3
    const int u  = t & 63;
    const int rq = u >> 4;          // owns rows rq*4..rq*4+3
    const int c0 = (u & 15) << 2;   // owns cols c0..c0+3

    float* mgvp = sgvp + pg * 1024;
    float* mbf  = sbf  + pg * 1024;
    const float* mrow = mbf + (rq * 4) * 64;

    // hoisted positional-branch weights (loop-invariant)
    const float4 wpx = *(const float4*)(swp + c0);
    const float4 wpy = *(const float4*)(swp + 64 + c0);
    const float4 wpz = *(const float4*)(swp + 128 + c0);
    const float4 bp4 = *(const float4*)(sbias + c0);
    const float4 gp4 = *(const float4*)(sbias + 64 + c0);
    const float4 bt4 = *(const float4*)(sbias + 128 + c0);

    for (int iter = 0; iter < 4; iter++) {
        const int n = blockIdx.x * 16 + iter * 4 + pg;
        const bool valid = (n < N);
        const int nn = valid ? n : 0;

        const float4 q4 = *(const float4*)(g_q + nn * 64 + c0);
        const float ptx = points[nn * 3 + 0];
        const float pty = points[nn * 3 + 1];
        const float ptz = points[nn * 3 + 2];

        // --- gather + positional LN/relu (analytic stats) + attn_in ---
#pragma unroll
        for (int jj = 0; jj < 4; jj++) {
            const int r = rq * 4 + jj;
            const int id = nbr[nn * 16 + r];
            const float rx = points[id * 3 + 0] - ptx;
            const float ry = points[id * 3 + 1] - pty;
            const float rz = points[id * 3 + 2] - ptz;

            // analytic mean/var of row p = rel @ wp + bp over 64 channels
            const float s1 = fmaf(rx, sM[16], fmaf(ry, sM[17],
                             fmaf(rz, sM[18], sM[19])));
            const float tx = fmaf(rx, sM[0],  fmaf(ry, sM[1],
                             fmaf(rz, sM[2],  sM[3])));
            const float ty = fmaf(rx, sM[4],  fmaf(ry, sM[5],
                             fmaf(rz, sM[6],  sM[7])));
            const float tz = fmaf(rx, sM[8],  fmaf(ry, sM[9],
                             fmaf(rz, sM[10], sM[11])));
            const float tw = fmaf(rx, sM[12], fmaf(ry, sM[13],
                             fmaf(rz, sM[14], sM[15])));
            const float s2 = fmaf(rx, tx, fmaf(ry, ty, fmaf(rz, tz, tw)));
            const float mean = s1 * 0.015625f;
            const float var  = s2 * 0.015625f - mean * mean;
            const float inv  = rsqrtf(var + LN_EPS);

            float pr[4];
            pr[0] = fmaf(rx, wpx.x, fmaf(ry, wpy.x, fmaf(rz, wpz.x, bp4.x)));
            pr[1] = fmaf(rx, wpx.y, fmaf(ry, wpy.y, fmaf(rz, wpz.y, bp4.y)));
            pr[2] = fmaf(rx, wpx.z, fmaf(ry, wpy.z, fmaf(rz, wpz.z, bp4.z)));
            pr[3] = fmaf(rx, wpx.w, fmaf(ry, wpy.w, fmaf(rz, wpz.w, bp4.w)));

            float pv[4];
            pv[0] = fmaxf(fmaf((pr[0] - mean) * inv, gp4.x, bt4.x), 0.f);
            pv[1] = fmaxf(fmaf((pr[1] - mean) * inv, gp4.y, bt4.y), 0.f);
            pv[2] = fmaxf(fmaf((pr[2] - mean) * inv, gp4.z, bt4.z), 0.f);
            pv[3] = fmaxf(fmaf((pr[3] - mean) * inv, gp4.w, bt4.w), 0.f);

            const float4 gk4 = *(const float4*)(g_k + id * 64 + c0);
            const float4 gv4 = *(const float4*)(g_v + id * 64 + c0);

            *(float4*)(mbf + r * 64 + c0) =
                make_float4(q4.x - gk4.x + pv[0], q4.y - gk4.y + pv[1],
                            q4.z - gk4.z + pv[2], q4.w - gk4.w + pv[3]);
            *(float4*)(mgvp + r * 64 + c0) =
                make_float4(gv4.x + pv[0], gv4.y + pv[1],
                            gv4.z + pv[2], gv4.w + pv[3]);
        }
        __syncwarp();   // rows are shared only within this warp

        // --- GEMM1: h = relu(LN(attn_in @ wg1 + bg1)) ---
        float acc[4][4];
#pragma unroll
        for (int jj = 0; jj < 4; jj++)
#pragma unroll
            for (int j = 0; j < 4; j++) acc[jj][j] = sbias[192 + c0 + j];

#pragma unroll 2
        for (int i4 = 0; i4 < 16; i4++) {
            float a0[4], a1[4], a2[4], a3[4];
            *(float4*)a0 = *(const float4*)(mrow + 0 * 64 + i4 * 4);
            *(float4*)a1 = *(const float4*)(mrow + 1 * 64 + i4 * 4);
            *(float4*)a2 = *(const float4*)(mrow + 2 * 64 + i4 * 4);
            *(float4*)a3 = *(const float4*)(mrow + 3 * 64 + i4 * 4);
#pragma unroll
            for (int j = 0; j < 4; j++) {
                const float4 w4 = *(const float4*)(swg1 + (i4 * 4 + j) * 64 + c0);
                acc[0][0] = fmaf(a0[j], w4.x, acc[0][0]);
                acc[0][1] = fmaf(a0[j], w4.y, acc[0][1]);
                acc[0][2] = fmaf(a0[j], w4.z, acc[0][2]);
                acc[0][3] = fmaf(a0[j], w4.w, acc[0][3]);
                acc[1][0] = fmaf(a1[j], w4.x, acc[1][0]);
                acc[1][1] = fmaf(a1[j], w4.y, acc[1][1]);
                acc[1][2] = fmaf(a1[j], w4.z, acc[1][2]);
                acc[1][3] = fmaf(a1[j], w4.w, acc[1][3]);
                acc[2][0] = fmaf(a2[j], w4.x, acc[2][0]);
                acc[2][1] = fmaf(a2[j], w4.y, acc[2][1]);
                acc[2][2] = fmaf(a2[j], w4.z, acc[2][2]);
                acc[2][3] = fmaf(a2[j], w4.w, acc[2][3]);
                acc[3][0] = fmaf(a3[j], w4.x, acc[3][0]);
                acc[3][1] = fmaf(a3[j], w4.y, acc[3][1]);
                acc[3][2] = fmaf(a3[j], w4.z, acc[3][2]);
                acc[3][3] = fmaf(a3[j], w4.w, acc[3][3]);
            }
        }
#pragma unroll
        for (int jj = 0; jj < 4; jj++) {
            float s1 = acc[jj][0] + acc[jj][1] + acc[jj][2] + acc[jj][3];
            float s2 = acc[jj][0]*acc[jj][0] + acc[jj][1]*acc[jj][1]
                     + acc[jj][2]*acc[jj][2] + acc[jj][3]*acc[jj][3];
            reduce16(s1, s2);
            const float mean = s1 * 0.015625f;
            const float var  = s2 * 0.015625f - mean * mean;
            const float inv  = rsqrtf(var + LN_EPS);
#pragma unroll
            for (int j = 0; j < 4; j++) {
                const int c = c0 + j;
                acc[jj][j] = fmaxf(fmaf((acc[jj][j] - mean) * inv,
                                        sbias[256 + c], sbias[320 + c]), 0.f);
            }
        }
        // reduce16's shfl converged the warp; all reads of mbf rows are done
#pragma unroll
        for (int jj = 0; jj < 4; jj++)
            *(float4*)(mbf + (rq * 4 + jj) * 64 + c0) =
                make_float4(acc[jj][0], acc[jj][1], acc[jj][2], acc[jj][3]);
        __syncwarp();

        // --- GEMM2: w = h @ wg2 + bg2 ---
        float acc2[4][4];
#pragma unroll
        for (int jj = 0; jj < 4; jj++)
#pragma unroll
            for (int j = 0; j < 4; j++) acc2[jj][j] = sbias[384 + c0 + j];

#pragma unroll 2
        for (int i4 = 0; i4 < 16; i4++) {
            float a0[4], a1[4], a2[4], a3[4];
            *(float4*)a0 = *(const float4*)(mrow + 0 * 64 + i4 * 4);
            *(float4*)a1 = *(const float4*)(mrow + 1 * 64 + i4 * 4);
            *(float4*)a2 = *(const float4*)(mrow + 2 * 64 + i4 * 4);
            *(float4*)a3 = *(const float4*)(mrow + 3 * 64 + i4 * 4);
#pragma unroll
            for (int j = 0; j < 4; j++) {
                const float4 w4 = *(const float4*)(swg2 + (i4 * 4 + j) * 64 + c0);
                acc2[0][0] = fmaf(a0[j], w4.x, acc2[0][0]);
                acc2[0][1] = fmaf(a0[j], w4.y, acc2[0][1]);
                acc2[0][2] = fmaf(a0[j], w4.z, acc2[0][2]);
                acc2[0][3] = fmaf(a0[j], w4.w, acc2[0][3]);
                acc2[1][0] = fmaf(a1[j], w4.x, acc2[1][0]);
                acc2[1][1] = fmaf(a1[j], w4.y, acc2[1][1]);
                acc2[1][2] = fmaf(a1[j], w4.z, acc2[1][2]);
                acc2[1][3] = fmaf(a1[j], w4.w, acc2[1][3]);
                acc2[2][0] = fmaf(a2[j], w4.x, acc2[2][0]);
                acc2[2][1] = fmaf(a2[j], w4.y, acc2[2][1]);
                acc2[2][2] = fmaf(a2[j], w4.z, acc2[2][2]);
                acc2[2][3] = fmaf(a2[j], w4.w, acc2[2][3]);
                acc2[3][0] = fmaf(a3[j], w4.x, acc2[3][0]);
                acc2[3][1] = fmaf(a3[j], w4.y, acc2[3][1]);
                acc2[3][2] = fmaf(a3[j], w4.z, acc2[3][2]);
                acc2[3][3] = fmaf(a3[j], w4.w, acc2[3][3]);
            }
        }
        __syncwarp();
#pragma unroll
        for (int jj = 0; jj < 4; jj++)
            *(float4*)(mbf + (rq * 4 + jj) * 64 + c0) =
                make_float4(acc2[jj][0], acc2[jj][1], acc2[jj][2], acc2[jj][3]);
        __syncthreads();   // softmax reads columns across all warps

        // --- softmax over K + weighted sum; thread u owns column u ---
        float mx = -3.4e38f;
#pragma unroll
        for (int kk = 0; kk < 16; kk++) mx = fmaxf(mx, mbf[kk * 64 + u]);
        float s = 0.f, o = 0.f;
#pragma unroll
        for (int kk = 0; kk < 16; kk++) {
            const float e = __expf(mbf[kk * 64 + u] - mx);
            s += e;
            o = fmaf(e, mgvp[kk * 64 + u], o);
        }
        smout[(iter * 4 + pg) * 64 + u] = __fdividef(o, s);
        __syncthreads();   // protect tiles before next iteration
    }

    // --- batched final: out = mout @ wo + bo + residual, 16 points at once ---
    {
        const int row = t >> 4;          // 0..15: point within block
        const int cg4 = (t & 15) << 2;   // column group
        const int n2 = blockIdx.x * 16 + row;
        float acc3[4];
#pragma unroll
        for (int j = 0; j < 4; j++) acc3[j] = sbias[448 + cg4 + j];

        const float* morow = smout + row * 64;
#pragma unroll 4
        for (int i4 = 0; i4 < 16; i4++) {
            float a[4];
            *(float4*)a = *(const float4*)(morow + i4 * 4);
#pragma unroll
            for (int j = 0; j < 4; j++) {
                const float4 w4 = *(const float4*)(wo + (i4 * 4 + j) * 64 + cg4);
                acc3[0] = fmaf(a[j], w4.x, acc3[0]);
                acc3[1] = fmaf(a[j], w4.y, acc3[1]);
                acc3[2] = fmaf(a[j], w4.z, acc3[2]);
                acc3[3] = fmaf(a[j], w4.w, acc3[3]);
            }
        }
        if (n2 < N) {
            const float4 f4 = *(const float4*)(feat + n2 * 64 + cg4);
            *(float4*)(out + n2 * 64 + cg4) =
                make_float4(acc3[0] + f4.x, acc3[1] + f4.y,
                            acc3[2] + f4.z, acc3[3] + f4.w);
        }
    }
}

// ---------------------------------------------------------------------------
extern "C" void kernel_launch(void* const* d_in, const int* in_sizes, int n_in,
                              void* d_out, int out_size)
{
    const float* points = (const float*)d_in[0];
    const float* feat   = (const float*)d_in[1];
    const int*   nbr    = (const int*)  d_in[2];
    const float* wq     = (const float*)d_in[3];
    const float* bq     = (const float*)d_in[4];
    const float* wk     = (const float*)d_in[5];
    const float* bk     = (const float*)d_in[6];
    const float* wv     = (const float*)d_in[7];
    const float* bv     = (const float*)d_in[8];
    const float* wp     = (const float*)d_in[9];
    const float* bp     = (const float*)d_in[10];
    const float* gp     = (const float*)d_in[11];
    const float* betap  = (const float*)d_in[12];
    const float* wg1    = (const float*)d_in[13];
    const float* bg1    = (const float*)d_in[14];
    const float* gg     = (const float*)d_in[15];
    const float* betag  = (const float*)d_in[16];
    const float* wg2    = (const float*)d_in[17];
    const float* bg2    = (const float*)d_in[18];
    const float* wo     = (const float*)d_in[19];
    const float* bo     = (const float*)d_in[20];
    float* out = (float*)d_out;

    const int N = in_sizes[0] / 3;

    const int smemA = (3 * 4096 + 192 + 4096) * 4;                       // 66304
    const int smemB = (2 * 4096 + 192 + 512 + 32 + 2 * 4096 + 1024) * 4; // 72576
    cudaFuncSetAttribute(qkv_kernel,
                         cudaFuncAttributeMaxDynamicSharedMemorySize, smemA);
    cudaFuncSetAttribute(pt_kernel,
                         cudaFuncAttributeMaxDynamicSharedMemorySize, smemB);

    qkv_kernel<<<(N + 63) / 64, 1024, smemA>>>(feat, N, wq, bq, wk, bk, wv, bv);
    pt_kernel<<<(N + 15) / 16, 256, smemB>>>(points, feat, nbr, N,
                                             wp, wg1, wg2, wo,
                                             bp, gp, betap, bg1, gg, betag,
                                             bg2, bo, out);
}